// round 12
// baseline (speedup 1.0000x reference)
#include <cuda_runtime.h>
#include <cuda_bf16.h>
#include <cstdint>

// GraphNorm: out = weight * (x - mean[batch]*mean_scale) / std[batch] + bias
// batch is SORTED (int32 on device; probed) -> segment g = contiguous rows
// [lower_bound(g), lower_bound(g+1)).
//
// One-pass stats via E[x^2]:  var = E[x^2] + m^2 * s * (s - 2)
// Output affine per (segment, col): A = w*rsqrt(var+eps), B = bias - s*m*A.
//
// R12 design (from R5-R11 sweep):
//   - BW tracks count of *uncoupled* warps (small CTAs win).
//   - Pass-2 reuse needs (concurrent CTAs x per-CTA footprint) <= ~92 MB
//     in the L2 evict_last class (R8 fit, R9 thrashed).
//   - smem row-caching taxes the L1tex pipe (R11) — avoid.
//   => Split each segment across a 2-CTA CLUSTER: footprint/CTA halves
//      (62.5 KB) so 6 CTAs/SM x 148 = 55 MB fits easily, while keeping
//      48 small-CTA warps/SM. Stats combined via one DSMEM exchange +
//      cluster.sync (~380 cyc, negligible).
// Hints: pass-1 ld.v8 evict_last, pass-2 ld.v8 evict_first, st.cs stores.

#define EPS 1e-6f
#define NUM_SEGMENTS 4096   // fixed by problem setup (G)

__device__ __forceinline__ void ld8_keep(const float* p, float* v) {
    unsigned a0,a1,a2,a3,a4,a5,a6,a7;
    asm("ld.global.nc.L2::evict_last.v8.b32 {%0,%1,%2,%3,%4,%5,%6,%7}, [%8];"
        : "=r"(a0),"=r"(a1),"=r"(a2),"=r"(a3),
          "=r"(a4),"=r"(a5),"=r"(a6),"=r"(a7) : "l"(p));
    v[0]=__uint_as_float(a0); v[1]=__uint_as_float(a1);
    v[2]=__uint_as_float(a2); v[3]=__uint_as_float(a3);
    v[4]=__uint_as_float(a4); v[5]=__uint_as_float(a5);
    v[6]=__uint_as_float(a6); v[7]=__uint_as_float(a7);
}

__device__ __forceinline__ void ld8_done(const float* p, float* v) {
    unsigned a0,a1,a2,a3,a4,a5,a6,a7;
    asm("ld.global.nc.L2::evict_first.v8.b32 {%0,%1,%2,%3,%4,%5,%6,%7}, [%8];"
        : "=r"(a0),"=r"(a1),"=r"(a2),"=r"(a3),
          "=r"(a4),"=r"(a5),"=r"(a6),"=r"(a7) : "l"(p));
    v[0]=__uint_as_float(a0); v[1]=__uint_as_float(a1);
    v[2]=__uint_as_float(a2); v[3]=__uint_as_float(a3);
    v[4]=__uint_as_float(a4); v[5]=__uint_as_float(a5);
    v[6]=__uint_as_float(a6); v[7]=__uint_as_float(a7);
}

__device__ __forceinline__ void st4_stream(float* p, float a, float b, float c, float d) {
    asm volatile("st.global.cs.v4.f32 [%0], {%1,%2,%3,%4};"
                 :: "l"(p), "f"(a), "f"(b), "f"(c), "f"(d));
}

// Write one float into the PEER CTA's shared memory at the same offset.
__device__ __forceinline__ void st_peer_f32(uint32_t laddr, uint32_t peer_rank, float v) {
    uint32_t raddr;
    asm volatile("mapa.shared::cluster.u32 %0, %1, %2;"
                 : "=r"(raddr) : "r"(laddr), "r"(peer_rank));
    asm volatile("st.shared::cluster.f32 [%0], %1;"
                 :: "r"(raddr), "f"(v) : "memory");
}

__device__ __forceinline__ void cluster_sync_() {
    asm volatile("barrier.cluster.arrive.aligned;" ::: "memory");
    asm volatile("barrier.cluster.wait.aligned;"   ::: "memory");
}

__global__ __launch_bounds__(256, 6) __cluster_dims__(2, 1, 1)
void graphnorm_kernel(
    const float* __restrict__ x,
    const void* __restrict__ batch_raw,
    int n,
    const float* __restrict__ weight,
    const float* __restrict__ bias,
    const float* __restrict__ mean_scale,
    float* __restrict__ out)
{
    const int g    = blockIdx.x >> 1;   // segment id (cluster id)
    const int rank = blockIdx.x & 1;    // cluster CTA rank
    const int t = threadIdx.x;
    const int o = t & 15;   // octet: owns columns [8o, 8o+8)
    const int r = t >> 4;   // row-lane 0..15

    __shared__ int sBounds[2];
    __shared__ int sIsI64;
    __shared__ float s_sum[8][128];
    __shared__ float s_sq [8][128];
    __shared__ float s_peer[2][128];    // [0]=peer sum, [1]=peer sq
    __shared__ float sA[128];
    __shared__ float sB[128];

    // Dtype probe (in-bounds either way): largest odd u32 index j:
    // int32 -> value near 4095 (nonzero); int64 -> high word (zero).
    if (t == 0) {
        int j = n - 1;
        if ((j & 1) == 0) j -= 1;
        if (j < 1) j = 1;
        sIsI64 = (((const unsigned*)batch_raw)[j] == 0u) ? 1 : 0;
    }
    __syncthreads();
    const int isI64 = sIsI64;

    // Threads 0 and 1 each run one lower_bound over the sorted batch array.
    if (t < 2) {
        int key = g + t;
        int lo = 0, hi = n;
        if (isI64) {
            const long long* b64 = (const long long*)batch_raw;
            long long k = (long long)key;
            while (lo < hi) {
                int mid = (lo + hi) >> 1;
                if (__ldg(&b64[mid]) < k) lo = mid + 1; else hi = mid;
            }
        } else {
            const int* b32 = (const int*)batch_raw;
            while (lo < hi) {
                int mid = (lo + hi) >> 1;
                if (__ldg(&b32[mid]) < key) lo = mid + 1; else hi = mid;
            }
        }
        sBounds[t] = lo;
    }
    __syncthreads();

    const int s = sBounds[0];
    const int e = sBounds[1];
    const int cnt = e - s;   // full segment count (both ranks agree)
    // NOTE: no early return — cluster.sync below requires all CTAs.

    float sum[8] = {0,0,0,0,0,0,0,0};
    float sq [8] = {0,0,0,0,0,0,0,0};

    // Pass 1 over this rank's half: rows s + rank*16 + r, stride 32.
    const int row0 = s + rank * 16 + r;
    for (int i = row0; i < e; i += 32) {
        float v[8];
        ld8_keep(x + (size_t)i * 128 + o * 8, v);
        #pragma unroll
        for (int j = 0; j < 8; j++) {
            sum[j] += v[j];
            sq [j] += v[j] * v[j];
        }
    }

    // Warp-level pre-reduce: lanes 16-31 (row r+1) fold into lanes 0-15.
    #pragma unroll
    for (int j = 0; j < 8; j++) {
        sum[j] += __shfl_down_sync(0xffffffffu, sum[j], 16);
        sq [j] += __shfl_down_sync(0xffffffffu, sq [j], 16);
    }
    const int w = t >> 5;            // warp id = folded row 0..7
    if ((t & 16) == 0) {
        #pragma unroll
        for (int j = 0; j < 8; j++) {
            s_sum[w][o * 8 + j] = sum[j];
            s_sq [w][o * 8 + j] = sq[j];
        }
    }
    __syncthreads();

    // Tree reduce 8 rows -> 1 using 256 threads over 128 cols x 2 halves.
    {
        const int c = t & 127;
        const int h = t >> 7;        // 0 or 1
        s_sum[h][c] += s_sum[h + 4][c];  s_sum[h + 2][c] += s_sum[h + 6][c];
        s_sq [h][c] += s_sq [h + 4][c];  s_sq [h + 2][c] += s_sq [h + 6][c];
        __syncthreads();
        s_sum[h][c] += s_sum[h + 2][c];
        s_sq [h][c] += s_sq [h + 2][c];
        __syncthreads();
        if (h == 0) {
            s_sum[0][c] += s_sum[1][c];
            s_sq [0][c] += s_sq [1][c];
        }
    }
    __syncthreads();

    // Exchange CTA partials with the peer rank via DSMEM, then combine.
    {
        const int c = t & 127;
        const int h = t >> 7;        // 0: sum, 1: sq
        float own = (h == 0) ? s_sum[0][c] : s_sq[0][c];
        uint32_t laddr = (uint32_t)__cvta_generic_to_shared(&s_peer[h][c]);
        st_peer_f32(laddr, rank ^ 1, own);
        cluster_sync_();             // peer's partials now in s_peer
    }

    // One thread per column: combine halves, compute A, B into smem.
    if (t < 128 && cnt > 0) {
        float inv_cnt = 1.f / (float)cnt;
        float m  = (s_sum[0][t] + s_peer[0][t]) * inv_cnt;
        float ms = mean_scale[t];
        float var = (s_sq[0][t] + s_peer[1][t]) * inv_cnt
                    + m * m * ms * (ms - 2.f);
        float A = weight[t] * rsqrtf(var + EPS);
        sA[t] = A;
        sB[t] = bias[t] - m * ms * A;
    }
    __syncthreads();

    // Pass 2 over the same rows: L2-resident (evict_first), stream out (.cs).
    const float* __restrict__ pA = &sA[o * 8];
    const float* __restrict__ pB = &sB[o * 8];
    for (int i = row0; i < e; i += 32) {
        float v[8];
        ld8_done(x + (size_t)i * 128 + o * 8, v);
        float w0 = v[0] * pA[0] + pB[0];
        float w1 = v[1] * pA[1] + pB[1];
        float w2 = v[2] * pA[2] + pB[2];
        float w3 = v[3] * pA[3] + pB[3];
        float w4 = v[4] * pA[4] + pB[4];
        float w5 = v[5] * pA[5] + pB[5];
        float w6 = v[6] * pA[6] + pB[6];
        float w7 = v[7] * pA[7] + pB[7];
        float* op = out + (size_t)i * 128 + o * 8;
        st4_stream(op,     w0, w1, w2, w3);
        st4_stream(op + 4, w4, w5, w6, w7);
    }
}

extern "C" void kernel_launch(void* const* d_in, const int* in_sizes, int n_in,
                              void* d_out, int out_size) {
    const float* x          = (const float*)d_in[0];
    const void*  batch      = (const void*)d_in[1];
    // d_in[2] = num_segments (device scalar; grid sized by NUM_SEGMENTS)
    const float* weight     = (const float*)d_in[3];
    const float* bias       = (const float*)d_in[4];
    const float* mean_scale = (const float*)d_in[5];
    float*       out        = (float*)d_out;

    const int D = 128;
    const int N = in_sizes[0] / D;

    // 2 CTAs per segment (cluster pairs: blockIdx {2g, 2g+1}).
    graphnorm_kernel<<<NUM_SEGMENTS * 2, 256>>>(x, batch, N, weight, bias,
                                                mean_scale, out);
}

// round 13
// speedup vs baseline: 1.1539x; 1.1539x over previous
#include <cuda_runtime.h>
#include <cuda_bf16.h>
#include <cstdint>

// GraphNorm: out = weight * (x - mean[batch]*mean_scale) / std[batch] + bias
// batch is SORTED (int32 on device; probed) -> segment g = contiguous rows
// [lower_bound(g), lower_bound(g+1)).
//
// One-pass stats via E[x^2]:  var = E[x^2] + m^2 * s * (s - 2)
// Output affine per (segment, col): A = w*rsqrt(var+eps), B = bias - s*m*A.
//
// R13 synthesis of the R5-R12 sweep:
//   - BW is monotone in occupancy; only the 32-reg float4 shape (8 CTAs/SM,
//     ~90% occ) reached 6.1 TB/s (R5). v8-asm hint variants cost registers
//     and never exceeded 5.2.
//   - Traffic fix must not allocate registers: make pass-2 loads and all
//     stores NON-ALLOCATING in L2 (createpolicy evict_first + cache_hint,
//     which accepts v4 unlike the direct .L2::evict_* modifier; st.cs).
//     Then only pass-1 reads insert into L2 -> insertion rate halves ->
//     reuse distance ~74 MB < 126 MB L2 -> pass-2 hits under plain LRU,
//     even at 8 CTAs/SM. No evict_last class to overflow (R9 lesson).

#define EPS 1e-6f
#define NUM_SEGMENTS 4096   // fixed by problem setup (G)

__device__ __forceinline__ uint64_t mk_policy_evict_first() {
    uint64_t p;
    asm("createpolicy.fractional.L2::evict_first.b64 %0, 1.0;" : "=l"(p));
    return p;
}

// Pass-2 load: hit-and-demote / allocate-at-LRU (consume, don't pollute).
__device__ __forceinline__ float4 ld4_ef(const float4* p, uint64_t pol) {
    float4 v;
    asm("ld.global.nc.L2::cache_hint.v4.f32 {%0,%1,%2,%3}, [%4], %5;"
        : "=f"(v.x), "=f"(v.y), "=f"(v.z), "=f"(v.w) : "l"(p), "l"(pol));
    return v;
}

// Streaming store (evict-first class).
__device__ __forceinline__ void st4_stream(float4* p, float4 v) {
    asm volatile("st.global.cs.v4.f32 [%0], {%1,%2,%3,%4};"
                 :: "l"(p), "f"(v.x), "f"(v.y), "f"(v.z), "f"(v.w));
}

__global__ __launch_bounds__(256, 8) void graphnorm_kernel(
    const float* __restrict__ x,
    const void* __restrict__ batch_raw,
    int n,
    const float* __restrict__ weight,
    const float* __restrict__ bias,
    const float* __restrict__ mean_scale,
    float* __restrict__ out)
{
    const int g = blockIdx.x;
    const int t = threadIdx.x;
    const int q = t & 31;   // quad: owns columns [4q, 4q+4)
    const int r = t >> 5;   // row-lane 0..7: strides rows by 8

    __shared__ int sBounds[2];
    __shared__ int sIsI64;
    __shared__ float4 s_sum[8][32];
    __shared__ float4 s_sq [8][32];
    __shared__ float4 sA[32];
    __shared__ float4 sB[32];

    // Dtype probe (in-bounds either way): largest odd u32 index j:
    // int32 -> value near 4095 (nonzero); int64 -> high word (zero).
    if (t == 0) {
        int j = n - 1;
        if ((j & 1) == 0) j -= 1;
        if (j < 1) j = 1;
        sIsI64 = (((const unsigned*)batch_raw)[j] == 0u) ? 1 : 0;
    }
    __syncthreads();
    const int isI64 = sIsI64;

    // Threads 0 and 1 each run one lower_bound over the sorted batch array.
    if (t < 2) {
        int key = g + t;
        int lo = 0, hi = n;
        if (isI64) {
            const long long* b64 = (const long long*)batch_raw;
            long long k = (long long)key;
            while (lo < hi) {
                int mid = (lo + hi) >> 1;
                if (__ldg(&b64[mid]) < k) lo = mid + 1; else hi = mid;
            }
        } else {
            const int* b32 = (const int*)batch_raw;
            while (lo < hi) {
                int mid = (lo + hi) >> 1;
                if (__ldg(&b32[mid]) < key) lo = mid + 1; else hi = mid;
            }
        }
        sBounds[t] = lo;
    }
    __syncthreads();

    const int s = sBounds[0];
    const int e = sBounds[1];
    if (e <= s) return;   // empty segment

    const float4* __restrict__ xv = (const float4*)x;

    float4 sum = make_float4(0.f, 0.f, 0.f, 0.f);
    float4 sq  = make_float4(0.f, 0.f, 0.f, 0.f);

    // Pass 1: plain loads (default LRU — these are the only L2 allocators).
    for (int i = s + r; i < e; i += 8) {
        float4 v = xv[(size_t)i * 32 + q];
        sum.x += v.x; sum.y += v.y; sum.z += v.z; sum.w += v.w;
        sq.x  += v.x * v.x; sq.y += v.y * v.y;
        sq.z  += v.z * v.z; sq.w += v.w * v.w;
    }
    s_sum[r][q] = sum;
    s_sq [r][q] = sq;
    __syncthreads();

    // Cross-warp tree reduce over the 8 row-lanes.
    #pragma unroll
    for (int off = 4; off > 0; off >>= 1) {
        if (r < off) {
            float4 a = s_sum[r][q], b = s_sum[r + off][q];
            a.x += b.x; a.y += b.y; a.z += b.z; a.w += b.w;
            s_sum[r][q] = a;
            float4 c = s_sq[r][q], d = s_sq[r + off][q];
            c.x += d.x; c.y += d.y; c.z += d.z; c.w += d.w;
            s_sq[r][q] = c;
        }
        __syncthreads();
    }

    // Warp 0: per-column affine coefficients A, B.
    if (r == 0) {
        float inv_cnt = 1.f / (float)(e - s);
        float4 tsum = s_sum[0][q];
        float4 tsq  = s_sq [0][q];
        float4 w4   = ((const float4*)weight)[q];
        float4 b4   = ((const float4*)bias)[q];
        float4 ms4  = ((const float4*)mean_scale)[q];

        float4 A, B;
        {
            float m = tsum.x * inv_cnt;
            float var = tsq.x * inv_cnt + m * m * ms4.x * (ms4.x - 2.f);
            A.x = w4.x * rsqrtf(var + EPS);
            B.x = b4.x - m * ms4.x * A.x;
        }
        {
            float m = tsum.y * inv_cnt;
            float var = tsq.y * inv_cnt + m * m * ms4.y * (ms4.y - 2.f);
            A.y = w4.y * rsqrtf(var + EPS);
            B.y = b4.y - m * ms4.y * A.y;
        }
        {
            float m = tsum.z * inv_cnt;
            float var = tsq.z * inv_cnt + m * m * ms4.z * (ms4.z - 2.f);
            A.z = w4.z * rsqrtf(var + EPS);
            B.z = b4.z - m * ms4.z * A.z;
        }
        {
            float m = tsum.w * inv_cnt;
            float var = tsq.w * inv_cnt + m * m * ms4.w * (ms4.w - 2.f);
            A.w = w4.w * rsqrtf(var + EPS);
            B.w = b4.w - m * ms4.w * A.w;
        }
        sA[q] = A;
        sB[q] = B;
    }
    __syncthreads();

    const float4 A = sA[q];
    const float4 B = sB[q];
    float4* __restrict__ ov = (float4*)out;
    const uint64_t pol = mk_policy_evict_first();

    // Pass 2: non-allocating loads (hit pass-1 lines, demote them) and
    // streaming stores — neither inserts long-lived lines into L2.
    for (int i = s + r; i < e; i += 8) {
        float4 v = ld4_ef(&xv[(size_t)i * 32 + q], pol);
        float4 o;
        o.x = v.x * A.x + B.x;
        o.y = v.y * A.y + B.y;
        o.z = v.z * A.z + B.z;
        o.w = v.w * A.w + B.w;
        st4_stream(&ov[(size_t)i * 32 + q], o);
    }
}

extern "C" void kernel_launch(void* const* d_in, const int* in_sizes, int n_in,
                              void* d_out, int out_size) {
    const float* x          = (const float*)d_in[0];
    const void*  batch      = (const void*)d_in[1];
    // d_in[2] = num_segments (device scalar; grid sized by NUM_SEGMENTS)
    const float* weight     = (const float*)d_in[3];
    const float* bias       = (const float*)d_in[4];
    const float* mean_scale = (const float*)d_in[5];
    float*       out        = (float*)d_out;

    const int D = 128;
    const int N = in_sizes[0] / D;

    graphnorm_kernel<<<NUM_SEGMENTS, 256>>>(x, batch, N, weight, bias,
                                            mean_scale, out);
}

// round 14
// speedup vs baseline: 1.3024x; 1.1287x over previous
#include <cuda_runtime.h>
#include <cuda_bf16.h>
#include <cstdint>

// GraphNorm: out = weight * (x - mean[batch]*mean_scale) / std[batch] + bias
// batch is SORTED (int32 on device; probed) -> segment g = contiguous rows
// [lower_bound(g), lower_bound(g+1)).
//
// One-pass stats via E[x^2]:  var = E[x^2] + m^2 * s * (s - 2)
// Output affine per (segment, col): A = w*rsqrt(var+eps), B = bias - s*m*A.
//
// R14 = R13 + R12's good halves:
//   - R13 proved: 32-reg float4 shape -> 90% occ, 5.84 TB/s; non-allocating
//     pass-2 loads (createpolicy evict_first + cache_hint) + st.cs.
//     Residual: pass-1 reuse distance 1184 CTAs x 125 KB = 148 MB > L2.
//   - R12 proved: 2-CTA cluster split halves bytes/CTA; rows partition by
//     rank so total insertion footprint = 1184 x 62.5 KB = 74 MB < 126 MB.
//   => cluster-2 split ON TOP of the 32-reg shape. Stats combined via one
//      256-float DSMEM exchange + cluster.sync (~380 cyc, negligible).

#define EPS 1e-6f
#define NUM_SEGMENTS 4096   // fixed by problem setup (G)

__device__ __forceinline__ uint64_t mk_policy_evict_first() {
    uint64_t p;
    asm("createpolicy.fractional.L2::evict_first.b64 %0, 1.0;" : "=l"(p));
    return p;
}

// Pass-2 load: hit-and-demote / allocate-at-LRU (consume, don't pollute).
__device__ __forceinline__ float4 ld4_ef(const float4* p, uint64_t pol) {
    float4 v;
    asm("ld.global.nc.L2::cache_hint.v4.f32 {%0,%1,%2,%3}, [%4], %5;"
        : "=f"(v.x), "=f"(v.y), "=f"(v.z), "=f"(v.w) : "l"(p), "l"(pol));
    return v;
}

// Streaming store (evict-first class).
__device__ __forceinline__ void st4_stream(float4* p, float4 v) {
    asm volatile("st.global.cs.v4.f32 [%0], {%1,%2,%3,%4};"
                 :: "l"(p), "f"(v.x), "f"(v.y), "f"(v.z), "f"(v.w));
}

// Write one float into the PEER CTA's shared memory at the same offset.
__device__ __forceinline__ void st_peer_f32(uint32_t laddr, uint32_t peer_rank, float v) {
    uint32_t raddr;
    asm volatile("mapa.shared::cluster.u32 %0, %1, %2;"
                 : "=r"(raddr) : "r"(laddr), "r"(peer_rank));
    asm volatile("st.shared::cluster.f32 [%0], %1;"
                 :: "r"(raddr), "f"(v) : "memory");
}

__device__ __forceinline__ void cluster_sync_() {
    asm volatile("barrier.cluster.arrive.aligned;" ::: "memory");
    asm volatile("barrier.cluster.wait.aligned;"   ::: "memory");
}

__global__ __launch_bounds__(256, 8) __cluster_dims__(2, 1, 1)
void graphnorm_kernel(
    const float* __restrict__ x,
    const void* __restrict__ batch_raw,
    int n,
    const float* __restrict__ weight,
    const float* __restrict__ bias,
    const float* __restrict__ mean_scale,
    float* __restrict__ out)
{
    const int g    = blockIdx.x >> 1;   // segment id (cluster id)
    const int rank = blockIdx.x & 1;    // cluster CTA rank
    const int t = threadIdx.x;
    const int q = t & 31;   // quad: owns columns [4q, 4q+4)
    const int r = t >> 5;   // row-lane 0..7

    __shared__ int sBounds[2];
    __shared__ int sIsI64;
    __shared__ float4 s_sum[8][32];
    __shared__ float4 s_sq [8][32];
    __shared__ float  s_peer[2][128];   // [0]=peer sum, [1]=peer sq
    __shared__ float4 sA[32];
    __shared__ float4 sB[32];

    // Dtype probe (in-bounds either way): largest odd u32 index j:
    // int32 -> value near 4095 (nonzero); int64 -> high word (zero).
    if (t == 0) {
        int j = n - 1;
        if ((j & 1) == 0) j -= 1;
        if (j < 1) j = 1;
        sIsI64 = (((const unsigned*)batch_raw)[j] == 0u) ? 1 : 0;
    }
    __syncthreads();
    const int isI64 = sIsI64;

    // Threads 0 and 1 each run one lower_bound over the sorted batch array.
    if (t < 2) {
        int key = g + t;
        int lo = 0, hi = n;
        if (isI64) {
            const long long* b64 = (const long long*)batch_raw;
            long long k = (long long)key;
            while (lo < hi) {
                int mid = (lo + hi) >> 1;
                if (__ldg(&b64[mid]) < k) lo = mid + 1; else hi = mid;
            }
        } else {
            const int* b32 = (const int*)batch_raw;
            while (lo < hi) {
                int mid = (lo + hi) >> 1;
                if (__ldg(&b32[mid]) < key) lo = mid + 1; else hi = mid;
            }
        }
        sBounds[t] = lo;
    }
    __syncthreads();

    const int s = sBounds[0];
    const int e = sBounds[1];
    const int cnt = e - s;
    // NOTE: no early return — cluster.sync below requires all CTAs.

    const float4* __restrict__ xv = (const float4*)x;

    float4 sum = make_float4(0.f, 0.f, 0.f, 0.f);
    float4 sq  = make_float4(0.f, 0.f, 0.f, 0.f);

    // Pass 1 over this rank's rows (s + rank*8 + r, stride 16): plain loads
    // — the ONLY L2 allocators in this kernel.
    const int row0 = s + rank * 8 + r;
    for (int i = row0; i < e; i += 16) {
        float4 v = xv[(size_t)i * 32 + q];
        sum.x += v.x; sum.y += v.y; sum.z += v.z; sum.w += v.w;
        sq.x  += v.x * v.x; sq.y += v.y * v.y;
        sq.z  += v.z * v.z; sq.w += v.w * v.w;
    }
    s_sum[r][q] = sum;
    s_sq [r][q] = sq;
    __syncthreads();

    // Cross-warp tree reduce over the 8 row-lanes.
    #pragma unroll
    for (int off = 4; off > 0; off >>= 1) {
        if (r < off) {
            float4 a = s_sum[r][q], b = s_sum[r + off][q];
            a.x += b.x; a.y += b.y; a.z += b.z; a.w += b.w;
            s_sum[r][q] = a;
            float4 c = s_sq[r][q], d = s_sq[r + off][q];
            c.x += d.x; c.y += d.y; c.z += d.z; c.w += d.w;
            s_sq[r][q] = c;
        }
        __syncthreads();
    }

    // Exchange CTA partials with the peer rank via DSMEM.
    {
        const int c = t & 127;
        const int h = t >> 7;        // 0: sum, 1: sq
        const float* own = (h == 0) ? (const float*)&s_sum[0][0]
                                    : (const float*)&s_sq[0][0];
        uint32_t laddr = (uint32_t)__cvta_generic_to_shared(&s_peer[h][c]);
        st_peer_f32(laddr, rank ^ 1, own[c]);
        cluster_sync_();             // peer's partials now in s_peer
    }

    // Warp 0: combine halves, per-column affine coefficients A, B.
    if (r == 0 && cnt > 0) {
        float inv_cnt = 1.f / (float)cnt;
        const float* psum = &s_peer[0][q * 4];
        const float* psq  = &s_peer[1][q * 4];
        float4 tsum = s_sum[0][q];
        float4 tsq  = s_sq [0][q];
        tsum.x += psum[0]; tsum.y += psum[1]; tsum.z += psum[2]; tsum.w += psum[3];
        tsq.x  += psq[0];  tsq.y  += psq[1];  tsq.z  += psq[2];  tsq.w  += psq[3];
        float4 w4   = ((const float4*)weight)[q];
        float4 b4   = ((const float4*)bias)[q];
        float4 ms4  = ((const float4*)mean_scale)[q];

        float4 A, B;
        {
            float m = tsum.x * inv_cnt;
            float var = tsq.x * inv_cnt + m * m * ms4.x * (ms4.x - 2.f);
            A.x = w4.x * rsqrtf(var + EPS);
            B.x = b4.x - m * ms4.x * A.x;
        }
        {
            float m = tsum.y * inv_cnt;
            float var = tsq.y * inv_cnt + m * m * ms4.y * (ms4.y - 2.f);
            A.y = w4.y * rsqrtf(var + EPS);
            B.y = b4.y - m * ms4.y * A.y;
        }
        {
            float m = tsum.z * inv_cnt;
            float var = tsq.z * inv_cnt + m * m * ms4.z * (ms4.z - 2.f);
            A.z = w4.z * rsqrtf(var + EPS);
            B.z = b4.z - m * ms4.z * A.z;
        }
        {
            float m = tsum.w * inv_cnt;
            float var = tsq.w * inv_cnt + m * m * ms4.w * (ms4.w - 2.f);
            A.w = w4.w * rsqrtf(var + EPS);
            B.w = b4.w - m * ms4.w * A.w;
        }
        sA[q] = A;
        sB[q] = B;
    }
    __syncthreads();

    const float4 A = sA[q];
    const float4 B = sB[q];
    float4* __restrict__ ov = (float4*)out;
    const uint64_t pol = mk_policy_evict_first();

    // Pass 2 over the same rows: non-allocating loads (hit pass-1 lines,
    // demote) and streaming stores — neither inserts long-lived L2 lines.
    for (int i = row0; i < e; i += 16) {
        float4 v = ld4_ef(&xv[(size_t)i * 32 + q], pol);
        float4 o;
        o.x = v.x * A.x + B.x;
        o.y = v.y * A.y + B.y;
        o.z = v.z * A.z + B.z;
        o.w = v.w * A.w + B.w;
        st4_stream(&ov[(size_t)i * 32 + q], o);
    }
}

extern "C" void kernel_launch(void* const* d_in, const int* in_sizes, int n_in,
                              void* d_out, int out_size) {
    const float* x          = (const float*)d_in[0];
    const void*  batch      = (const void*)d_in[1];
    // d_in[2] = num_segments (device scalar; grid sized by NUM_SEGMENTS)
    const float* weight     = (const float*)d_in[3];
    const float* bias       = (const float*)d_in[4];
    const float* mean_scale = (const float*)d_in[5];
    float*       out        = (float*)d_out;

    const int D = 128;
    const int N = in_sizes[0] / D;

    // 2 CTAs per segment (cluster pairs: blockIdx {2g, 2g+1}).
    graphnorm_kernel<<<NUM_SEGMENTS * 2, 256>>>(x, batch, N, weight, bias,
                                                mean_scale, out);
}

// round 15
// speedup vs baseline: 1.3966x; 1.0723x over previous
#include <cuda_runtime.h>
#include <cuda_bf16.h>
#include <cstdint>

// GraphNorm: out = weight * (x - mean[batch]*mean_scale) / std[batch] + bias
// batch is SORTED (int32 on device; probed) -> segment g = contiguous rows.
//
// One-pass stats via E[x^2]:  var = E[x^2] + m^2 * s * (s - 2)
// Output affine per (segment, col): A = w*rsqrt(var+eps), B = bias - s*m*A.
//
// R15 = R14 (cluster-2 split, 32-reg float4 shape, non-allocating pass-2 +
// st.cs; traffic at compulsory floor) MINUS the per-CTA prologue:
//   R14's 10% BW loss == 8192 CTAs x ~3.3us binary-search/probe idle.
//   Replace with precomputed bounds in __device__ scratch (sanctioned per
//   pitfalls.md): one scatter kernel over sorted batch (4 MB, ~1us), main
//   kernel reads 2 ints.

#define EPS 1e-6f
#define NUM_SEGMENTS 4096   // fixed by problem setup (G)

__device__ int g_start[NUM_SEGMENTS];
__device__ int g_end  [NUM_SEGMENTS];
__device__ int g_isI64;

__global__ void init_probe_kernel(const void* __restrict__ batch_raw, int n) {
    int i = blockIdx.x * blockDim.x + threadIdx.x;
    if (i < NUM_SEGMENTS) {
        g_start[i] = 0;
        g_end[i]   = 0;
    }
    if (i == 0) {
        // Dtype probe (in-bounds either way): largest odd u32 index j:
        // int32 -> value near 4095 (nonzero, sorted max); int64 -> high
        // word of an element (zero, values < 2^31).
        int j = n - 1;
        if ((j & 1) == 0) j -= 1;
        if (j < 1) j = 1;
        g_isI64 = (((const unsigned*)batch_raw)[j] == 0u) ? 1 : 0;
    }
}

__global__ void find_bounds_kernel(const void* __restrict__ batch_raw, int n) {
    int i = blockIdx.x * blockDim.x + threadIdx.x;
    if (i >= n) return;
    int b, prev = -1, next = -1;
    if (g_isI64) {
        const long long* p = (const long long*)batch_raw;
        b = (int)p[i];
        if (i > 0)     prev = (int)p[i - 1];
        if (i < n - 1) next = (int)p[i + 1];
    } else {
        const int* p = (const int*)batch_raw;
        b = p[i];
        if (i > 0)     prev = p[i - 1];
        if (i < n - 1) next = p[i + 1];
    }
    if (i == 0     || prev != b) g_start[b] = i;
    if (i == n - 1 || next != b) g_end[b]   = i + 1;
}

__device__ __forceinline__ uint64_t mk_policy_evict_first() {
    uint64_t p;
    asm("createpolicy.fractional.L2::evict_first.b64 %0, 1.0;" : "=l"(p));
    return p;
}

// Pass-2 load: hit-and-demote / allocate-at-LRU (consume, don't pollute).
__device__ __forceinline__ float4 ld4_ef(const float4* p, uint64_t pol) {
    float4 v;
    asm("ld.global.nc.L2::cache_hint.v4.f32 {%0,%1,%2,%3}, [%4], %5;"
        : "=f"(v.x), "=f"(v.y), "=f"(v.z), "=f"(v.w) : "l"(p), "l"(pol));
    return v;
}

// Streaming store (evict-first class).
__device__ __forceinline__ void st4_stream(float4* p, float4 v) {
    asm volatile("st.global.cs.v4.f32 [%0], {%1,%2,%3,%4};"
                 :: "l"(p), "f"(v.x), "f"(v.y), "f"(v.z), "f"(v.w));
}

// Write one float into the PEER CTA's shared memory at the same offset.
__device__ __forceinline__ void st_peer_f32(uint32_t laddr, uint32_t peer_rank, float v) {
    uint32_t raddr;
    asm volatile("mapa.shared::cluster.u32 %0, %1, %2;"
                 : "=r"(raddr) : "r"(laddr), "r"(peer_rank));
    asm volatile("st.shared::cluster.f32 [%0], %1;"
                 :: "r"(raddr), "f"(v) : "memory");
}

__device__ __forceinline__ void cluster_sync_() {
    asm volatile("barrier.cluster.arrive.aligned;" ::: "memory");
    asm volatile("barrier.cluster.wait.aligned;"   ::: "memory");
}

__global__ __launch_bounds__(256, 8) __cluster_dims__(2, 1, 1)
void graphnorm_kernel(
    const float* __restrict__ x,
    const float* __restrict__ weight,
    const float* __restrict__ bias,
    const float* __restrict__ mean_scale,
    float* __restrict__ out)
{
    const int g    = blockIdx.x >> 1;   // segment id (cluster id)
    const int rank = blockIdx.x & 1;    // cluster CTA rank
    const int t = threadIdx.x;
    const int q = t & 31;   // quad: owns columns [4q, 4q+4)
    const int r = t >> 5;   // row-lane 0..7

    __shared__ int sBounds[2];
    __shared__ float4 s_sum[8][32];
    __shared__ float4 s_sq [8][32];
    __shared__ float  s_peer[2][128];   // [0]=peer sum, [1]=peer sq
    __shared__ float4 sA[32];
    __shared__ float4 sB[32];

    // Prologue: just two int loads from precomputed bounds.
    if (t == 0) sBounds[0] = g_start[g];
    if (t == 1) sBounds[1] = g_end[g];
    __syncthreads();

    const int s = sBounds[0];
    const int e = sBounds[1];
    const int cnt = e - s;
    // NOTE: no early return — cluster.sync below requires all CTAs.

    const float4* __restrict__ xv = (const float4*)x;

    float4 sum = make_float4(0.f, 0.f, 0.f, 0.f);
    float4 sq  = make_float4(0.f, 0.f, 0.f, 0.f);

    // Pass 1 over this rank's rows (s + rank*8 + r, stride 16): plain loads
    // — the ONLY L2 allocators in this kernel.
    const int row0 = s + rank * 8 + r;
    for (int i = row0; i < e; i += 16) {
        float4 v = xv[(size_t)i * 32 + q];
        sum.x += v.x; sum.y += v.y; sum.z += v.z; sum.w += v.w;
        sq.x  += v.x * v.x; sq.y += v.y * v.y;
        sq.z  += v.z * v.z; sq.w += v.w * v.w;
    }
    s_sum[r][q] = sum;
    s_sq [r][q] = sq;
    __syncthreads();

    // Cross-warp tree reduce over the 8 row-lanes.
    #pragma unroll
    for (int off = 4; off > 0; off >>= 1) {
        if (r < off) {
            float4 a = s_sum[r][q], b = s_sum[r + off][q];
            a.x += b.x; a.y += b.y; a.z += b.z; a.w += b.w;
            s_sum[r][q] = a;
            float4 c = s_sq[r][q], d = s_sq[r + off][q];
            c.x += d.x; c.y += d.y; c.z += d.z; c.w += d.w;
            s_sq[r][q] = c;
        }
        __syncthreads();
    }

    // Exchange CTA partials with the peer rank via DSMEM.
    {
        const int c = t & 127;
        const int h = t >> 7;        // 0: sum, 1: sq
        const float* own = (h == 0) ? (const float*)&s_sum[0][0]
                                    : (const float*)&s_sq[0][0];
        uint32_t laddr = (uint32_t)__cvta_generic_to_shared(&s_peer[h][c]);
        st_peer_f32(laddr, rank ^ 1, own[c]);
        cluster_sync_();             // peer's partials now in s_peer
    }

    // Warp 0: combine halves, per-column affine coefficients A, B.
    if (r == 0 && cnt > 0) {
        float inv_cnt = 1.f / (float)cnt;
        const float* psum = &s_peer[0][q * 4];
        const float* psq  = &s_peer[1][q * 4];
        float4 tsum = s_sum[0][q];
        float4 tsq  = s_sq [0][q];
        tsum.x += psum[0]; tsum.y += psum[1]; tsum.z += psum[2]; tsum.w += psum[3];
        tsq.x  += psq[0];  tsq.y  += psq[1];  tsq.z  += psq[2];  tsq.w  += psq[3];
        float4 w4   = ((const float4*)weight)[q];
        float4 b4   = ((const float4*)bias)[q];
        float4 ms4  = ((const float4*)mean_scale)[q];

        float4 A, B;
        {
            float m = tsum.x * inv_cnt;
            float var = tsq.x * inv_cnt + m * m * ms4.x * (ms4.x - 2.f);
            A.x = w4.x * rsqrtf(var + EPS);
            B.x = b4.x - m * ms4.x * A.x;
        }
        {
            float m = tsum.y * inv_cnt;
            float var = tsq.y * inv_cnt + m * m * ms4.y * (ms4.y - 2.f);
            A.y = w4.y * rsqrtf(var + EPS);
            B.y = b4.y - m * ms4.y * A.y;
        }
        {
            float m = tsum.z * inv_cnt;
            float var = tsq.z * inv_cnt + m * m * ms4.z * (ms4.z - 2.f);
            A.z = w4.z * rsqrtf(var + EPS);
            B.z = b4.z - m * ms4.z * A.z;
        }
        {
            float m = tsum.w * inv_cnt;
            float var = tsq.w * inv_cnt + m * m * ms4.w * (ms4.w - 2.f);
            A.w = w4.w * rsqrtf(var + EPS);
            B.w = b4.w - m * ms4.w * A.w;
        }
        sA[q] = A;
        sB[q] = B;
    }
    __syncthreads();

    const float4 A = sA[q];
    const float4 B = sB[q];
    float4* __restrict__ ov = (float4*)out;
    const uint64_t pol = mk_policy_evict_first();

    // Pass 2 over the same rows: non-allocating loads (hit pass-1 lines,
    // demote) and streaming stores — neither inserts long-lived L2 lines.
    for (int i = row0; i < e; i += 16) {
        float4 v = ld4_ef(&xv[(size_t)i * 32 + q], pol);
        float4 o;
        o.x = v.x * A.x + B.x;
        o.y = v.y * A.y + B.y;
        o.z = v.z * A.z + B.z;
        o.w = v.w * A.w + B.w;
        st4_stream(&ov[(size_t)i * 32 + q], o);
    }
}

extern "C" void kernel_launch(void* const* d_in, const int* in_sizes, int n_in,
                              void* d_out, int out_size) {
    const float* x          = (const float*)d_in[0];
    const void*  batch      = (const void*)d_in[1];
    // d_in[2] = num_segments (device scalar; grid sized by NUM_SEGMENTS)
    const float* weight     = (const float*)d_in[3];
    const float* bias       = (const float*)d_in[4];
    const float* mean_scale = (const float*)d_in[5];
    float*       out        = (float*)d_out;

    const int D = 128;
    const int N = in_sizes[0] / D;

    init_probe_kernel<<<(NUM_SEGMENTS + 255) / 256, 256>>>(batch, N);
    find_bounds_kernel<<<(N + 255) / 256, 256>>>(batch, N);
    // 2 CTAs per segment (cluster pairs: blockIdx {2g, 2g+1}).
    graphnorm_kernel<<<NUM_SEGMENTS * 2, 256>>>(x, weight, bias,
                                                mean_scale, out);
}

// round 16
// speedup vs baseline: 1.4132x; 1.0119x over previous
#include <cuda_runtime.h>
#include <cuda_bf16.h>
#include <cstdint>

// GraphNorm: out = weight * (x - mean[batch]*mean_scale) / std[batch] + bias
// batch is SORTED (int32 on device; probed) -> segment g = contiguous rows.
//
// One-pass stats via E[x^2]:  var = E[x^2] + m^2 * s * (s - 2)
// Output affine per (segment, col): A = w*rsqrt(var+eps), B = bias - s*m*A.
//
// R16 = R15 minus the init kernel (4.4 us = 2.3% of total):
//   bounds kept as ONE array g_bound[G+1] filled by a gap-filling scatter
//   (every entry written every run -> no zero-init pass, no stale state;
//   empty segments get s==e naturally). Dtype probe folded into the
//   scatter kernel (per-block smem flag). Main kernel: R15 verbatim
//   (cluster-2 split, 32-reg float4 shape, plain pass-1 loads as sole L2
//   allocators, cache_hint evict_first pass-2, st.cs stores, DSMEM stat
//   exchange).

#define EPS 1e-6f
#define NUM_SEGMENTS 4096   // fixed by problem setup (G)

__device__ int g_bound[NUM_SEGMENTS + 1];   // segment g = rows [g_bound[g], g_bound[g+1])

__global__ void find_bounds_kernel(const void* __restrict__ batch_raw, int n) {
    __shared__ int sI64;
    if (threadIdx.x == 0) {
        // Dtype probe (in-bounds either way): largest odd u32 index j:
        // int32 -> value near 4095 (nonzero, sorted max); int64 -> high
        // word of an element (zero, values < 2^31).
        int j = n - 1;
        if ((j & 1) == 0) j -= 1;
        if (j < 1) j = 1;
        sI64 = (((const unsigned*)batch_raw)[j] == 0u) ? 1 : 0;
    }
    __syncthreads();

    int i = blockIdx.x * blockDim.x + threadIdx.x;
    if (i >= n) return;

    int b, prev = -1;
    if (sI64) {
        const long long* p = (const long long*)batch_raw;
        b = (int)p[i];
        if (i > 0) prev = (int)p[i - 1];
    } else {
        const int* p = (const int*)batch_raw;
        b = p[i];
        if (i > 0) prev = p[i - 1];
    }

    if (i == 0) {
        // Fill [0 .. b] with 0 (segments before the first value are empty).
        for (int v = 0; v <= b; v++) g_bound[v] = 0;
    } else if (prev != b) {
        // Boundary: segments (prev, b] all start at i.
        for (int v = prev + 1; v <= b; v++) g_bound[v] = i;
    }
    if (i == n - 1) {
        // Tail: segments (b, G] end at n.
        for (int v = b + 1; v <= NUM_SEGMENTS; v++) g_bound[v] = n;
    }
}

__device__ __forceinline__ uint64_t mk_policy_evict_first() {
    uint64_t p;
    asm("createpolicy.fractional.L2::evict_first.b64 %0, 1.0;" : "=l"(p));
    return p;
}

// Pass-2 load: hit-and-demote / allocate-at-LRU (consume, don't pollute).
__device__ __forceinline__ float4 ld4_ef(const float4* p, uint64_t pol) {
    float4 v;
    asm("ld.global.nc.L2::cache_hint.v4.f32 {%0,%1,%2,%3}, [%4], %5;"
        : "=f"(v.x), "=f"(v.y), "=f"(v.z), "=f"(v.w) : "l"(p), "l"(pol));
    return v;
}

// Streaming store (evict-first class).
__device__ __forceinline__ void st4_stream(float4* p, float4 v) {
    asm volatile("st.global.cs.v4.f32 [%0], {%1,%2,%3,%4};"
                 :: "l"(p), "f"(v.x), "f"(v.y), "f"(v.z), "f"(v.w));
}

// Write one float into the PEER CTA's shared memory at the same offset.
__device__ __forceinline__ void st_peer_f32(uint32_t laddr, uint32_t peer_rank, float v) {
    uint32_t raddr;
    asm volatile("mapa.shared::cluster.u32 %0, %1, %2;"
                 : "=r"(raddr) : "r"(laddr), "r"(peer_rank));
    asm volatile("st.shared::cluster.f32 [%0], %1;"
                 :: "r"(raddr), "f"(v) : "memory");
}

__device__ __forceinline__ void cluster_sync_() {
    asm volatile("barrier.cluster.arrive.aligned;" ::: "memory");
    asm volatile("barrier.cluster.wait.aligned;"   ::: "memory");
}

__global__ __launch_bounds__(256, 8) __cluster_dims__(2, 1, 1)
void graphnorm_kernel(
    const float* __restrict__ x,
    const float* __restrict__ weight,
    const float* __restrict__ bias,
    const float* __restrict__ mean_scale,
    float* __restrict__ out)
{
    const int g    = blockIdx.x >> 1;   // segment id (cluster id)
    const int rank = blockIdx.x & 1;    // cluster CTA rank
    const int t = threadIdx.x;
    const int q = t & 31;   // quad: owns columns [4q, 4q+4)
    const int r = t >> 5;   // row-lane 0..7

    __shared__ int sBounds[2];
    __shared__ float4 s_sum[8][32];
    __shared__ float4 s_sq [8][32];
    __shared__ float  s_peer[2][128];   // [0]=peer sum, [1]=peer sq
    __shared__ float4 sA[32];
    __shared__ float4 sB[32];

    // Prologue: two int loads from the precomputed bound array.
    if (t < 2) sBounds[t] = g_bound[g + t];
    __syncthreads();

    const int s = sBounds[0];
    const int e = sBounds[1];
    const int cnt = e - s;
    // NOTE: no early return — cluster.sync below requires all CTAs.

    const float4* __restrict__ xv = (const float4*)x;

    float4 sum = make_float4(0.f, 0.f, 0.f, 0.f);
    float4 sq  = make_float4(0.f, 0.f, 0.f, 0.f);

    // Pass 1 over this rank's rows (s + rank*8 + r, stride 16): plain loads
    // — the ONLY L2 allocators in this kernel.
    const int row0 = s + rank * 8 + r;
    for (int i = row0; i < e; i += 16) {
        float4 v = xv[(size_t)i * 32 + q];
        sum.x += v.x; sum.y += v.y; sum.z += v.z; sum.w += v.w;
        sq.x  += v.x * v.x; sq.y += v.y * v.y;
        sq.z  += v.z * v.z; sq.w += v.w * v.w;
    }
    s_sum[r][q] = sum;
    s_sq [r][q] = sq;
    __syncthreads();

    // Cross-warp tree reduce over the 8 row-lanes.
    #pragma unroll
    for (int off = 4; off > 0; off >>= 1) {
        if (r < off) {
            float4 a = s_sum[r][q], b = s_sum[r + off][q];
            a.x += b.x; a.y += b.y; a.z += b.z; a.w += b.w;
            s_sum[r][q] = a;
            float4 c = s_sq[r][q], d = s_sq[r + off][q];
            c.x += d.x; c.y += d.y; c.z += d.z; c.w += d.w;
            s_sq[r][q] = c;
        }
        __syncthreads();
    }

    // Exchange CTA partials with the peer rank via DSMEM.
    {
        const int c = t & 127;
        const int h = t >> 7;        // 0: sum, 1: sq
        const float* own = (h == 0) ? (const float*)&s_sum[0][0]
                                    : (const float*)&s_sq[0][0];
        uint32_t laddr = (uint32_t)__cvta_generic_to_shared(&s_peer[h][c]);
        st_peer_f32(laddr, rank ^ 1, own[c]);
        cluster_sync_();             // peer's partials now in s_peer
    }

    // Warp 0: combine halves, per-column affine coefficients A, B.
    if (r == 0 && cnt > 0) {
        float inv_cnt = 1.f / (float)cnt;
        const float* psum = &s_peer[0][q * 4];
        const float* psq  = &s_peer[1][q * 4];
        float4 tsum = s_sum[0][q];
        float4 tsq  = s_sq [0][q];
        tsum.x += psum[0]; tsum.y += psum[1]; tsum.z += psum[2]; tsum.w += psum[3];
        tsq.x  += psq[0];  tsq.y  += psq[1];  tsq.z  += psq[2];  tsq.w  += psq[3];
        float4 w4   = ((const float4*)weight)[q];
        float4 b4   = ((const float4*)bias)[q];
        float4 ms4  = ((const float4*)mean_scale)[q];

        float4 A, B;
        {
            float m = tsum.x * inv_cnt;
            float var = tsq.x * inv_cnt + m * m * ms4.x * (ms4.x - 2.f);
            A.x = w4.x * rsqrtf(var + EPS);
            B.x = b4.x - m * ms4.x * A.x;
        }
        {
            float m = tsum.y * inv_cnt;
            float var = tsq.y * inv_cnt + m * m * ms4.y * (ms4.y - 2.f);
            A.y = w4.y * rsqrtf(var + EPS);
            B.y = b4.y - m * ms4.y * A.y;
        }
        {
            float m = tsum.z * inv_cnt;
            float var = tsq.z * inv_cnt + m * m * ms4.z * (ms4.z - 2.f);
            A.z = w4.z * rsqrtf(var + EPS);
            B.z = b4.z - m * ms4.z * A.z;
        }
        {
            float m = tsum.w * inv_cnt;
            float var = tsq.w * inv_cnt + m * m * ms4.w * (ms4.w - 2.f);
            A.w = w4.w * rsqrtf(var + EPS);
            B.w = b4.w - m * ms4.w * A.w;
        }
        sA[q] = A;
        sB[q] = B;
    }
    __syncthreads();

    const float4 A = sA[q];
    const float4 B = sB[q];
    float4* __restrict__ ov = (float4*)out;
    const uint64_t pol = mk_policy_evict_first();

    // Pass 2 over the same rows: non-allocating loads (hit pass-1 lines,
    // demote) and streaming stores — neither inserts long-lived L2 lines.
    for (int i = row0; i < e; i += 16) {
        float4 v = ld4_ef(&xv[(size_t)i * 32 + q], pol);
        float4 o;
        o.x = v.x * A.x + B.x;
        o.y = v.y * A.y + B.y;
        o.z = v.z * A.z + B.z;
        o.w = v.w * A.w + B.w;
        st4_stream(&ov[(size_t)i * 32 + q], o);
    }
}

extern "C" void kernel_launch(void* const* d_in, const int* in_sizes, int n_in,
                              void* d_out, int out_size) {
    const float* x          = (const float*)d_in[0];
    const void*  batch      = (const void*)d_in[1];
    // d_in[2] = num_segments (device scalar; grid sized by NUM_SEGMENTS)
    const float* weight     = (const float*)d_in[3];
    const float* bias       = (const float*)d_in[4];
    const float* mean_scale = (const float*)d_in[5];
    float*       out        = (float*)d_out;

    const int D = 128;
    const int N = in_sizes[0] / D;

    find_bounds_kernel<<<(N + 255) / 256, 256>>>(batch, N);
    // 2 CTAs per segment (cluster pairs: blockIdx {2g, 2g+1}).
    graphnorm_kernel<<<NUM_SEGMENTS * 2, 256>>>(x, weight, bias,
                                                mean_scale, out);
}

// round 17
// speedup vs baseline: 1.4743x; 1.0432x over previous
#include <cuda_runtime.h>
#include <cuda_bf16.h>
#include <cstdint>

// GraphNorm: out = weight * (x - mean[batch]*mean_scale) / std[batch] + bias
// batch is SORTED (int32 on device; probed) -> segment g = contiguous rows.
//
// One-pass stats via E[x^2]:  var = E[x^2] + m^2 * s * (s - 2)
// Output affine per (segment, col): A = w*rsqrt(var+eps), B = bias - s*m*A.
//
// R17 = R16 (main kernel at 5.99 TB/s / ~compulsory traffic; frozen) with
// the two remaining shavings:
//   1. find_bounds vectorized 4x (int4 loads, 1/4 the threads).
//   2. main-loop addressing strength-reduced to pointer increments.

#define EPS 1e-6f
#define NUM_SEGMENTS 4096   // fixed by problem setup (G)

__device__ int g_bound[NUM_SEGMENTS + 1];   // segment g = rows [g_bound[g], g_bound[g+1])

// Gap-filling scatter over the sorted batch array: every g_bound entry is
// written every run (no init pass, no stale state). Each thread handles 4
// consecutive elements via one int4 load (int32 path; int64 fallback scalar).
__global__ void find_bounds_kernel(const void* __restrict__ batch_raw, int n) {
    __shared__ int sI64;
    if (threadIdx.x == 0) {
        // Dtype probe (in-bounds either way): largest odd u32 index j:
        // int32 -> value near 4095 (nonzero, sorted max); int64 -> high
        // word of an element (zero, values < 2^31).
        int j = n - 1;
        if ((j & 1) == 0) j -= 1;
        if (j < 1) j = 1;
        sI64 = (((const unsigned*)batch_raw)[j] == 0u) ? 1 : 0;
    }
    __syncthreads();

    const int base = (blockIdx.x * blockDim.x + threadIdx.x) * 4;
    if (base >= n) return;

    int v[4];
    int prev;
    int m = n - base; if (m > 4) m = 4;   // elements this thread owns

    if (!sI64) {
        const int* p = (const int*)batch_raw;
        if (((base + 4) <= n)) {
            int4 q4 = *(const int4*)(p + base);   // n % 4 == 0 in practice
            v[0] = q4.x; v[1] = q4.y; v[2] = q4.z; v[3] = q4.w;
        } else {
            for (int j = 0; j < m; j++) v[j] = p[base + j];
        }
        prev = (base == 0) ? -1 : p[base - 1];
    } else {
        const long long* p = (const long long*)batch_raw;
        for (int j = 0; j < m; j++) v[j] = (int)p[base + j];
        prev = (base == 0) ? -1 : (int)p[base - 1];
    }

    #pragma unroll
    for (int j = 0; j < 4; j++) {
        if (j >= m) break;
        const int b = v[j];
        const int i = base + j;
        if (i == 0) {
            for (int s = 0; s <= b; s++) g_bound[s] = 0;   // leading empties
        } else if (prev != b) {
            for (int s = prev + 1; s <= b; s++) g_bound[s] = i;
        }
        if (i == n - 1) {
            for (int s = b + 1; s <= NUM_SEGMENTS; s++) g_bound[s] = n;
        }
        prev = b;
    }
}

__device__ __forceinline__ uint64_t mk_policy_evict_first() {
    uint64_t p;
    asm("createpolicy.fractional.L2::evict_first.b64 %0, 1.0;" : "=l"(p));
    return p;
}

// Pass-2 load: hit-and-demote / allocate-at-LRU (consume, don't pollute).
__device__ __forceinline__ float4 ld4_ef(const float4* p, uint64_t pol) {
    float4 v;
    asm("ld.global.nc.L2::cache_hint.v4.f32 {%0,%1,%2,%3}, [%4], %5;"
        : "=f"(v.x), "=f"(v.y), "=f"(v.z), "=f"(v.w) : "l"(p), "l"(pol));
    return v;
}

// Streaming store (evict-first class).
__device__ __forceinline__ void st4_stream(float4* p, float4 v) {
    asm volatile("st.global.cs.v4.f32 [%0], {%1,%2,%3,%4};"
                 :: "l"(p), "f"(v.x), "f"(v.y), "f"(v.z), "f"(v.w));
}

// Write one float into the PEER CTA's shared memory at the same offset.
__device__ __forceinline__ void st_peer_f32(uint32_t laddr, uint32_t peer_rank, float v) {
    uint32_t raddr;
    asm volatile("mapa.shared::cluster.u32 %0, %1, %2;"
                 : "=r"(raddr) : "r"(laddr), "r"(peer_rank));
    asm volatile("st.shared::cluster.f32 [%0], %1;"
                 :: "r"(raddr), "f"(v) : "memory");
}

__device__ __forceinline__ void cluster_sync_() {
    asm volatile("barrier.cluster.arrive.aligned;" ::: "memory");
    asm volatile("barrier.cluster.wait.aligned;"   ::: "memory");
}

__global__ __launch_bounds__(256, 8) __cluster_dims__(2, 1, 1)
void graphnorm_kernel(
    const float* __restrict__ x,
    const float* __restrict__ weight,
    const float* __restrict__ bias,
    const float* __restrict__ mean_scale,
    float* __restrict__ out)
{
    const int g    = blockIdx.x >> 1;   // segment id (cluster id)
    const int rank = blockIdx.x & 1;    // cluster CTA rank
    const int t = threadIdx.x;
    const int q = t & 31;   // quad: owns columns [4q, 4q+4)
    const int r = t >> 5;   // row-lane 0..7

    __shared__ int sBounds[2];
    __shared__ float4 s_sum[8][32];
    __shared__ float4 s_sq [8][32];
    __shared__ float  s_peer[2][128];   // [0]=peer sum, [1]=peer sq
    __shared__ float4 sA[32];
    __shared__ float4 sB[32];

    // Prologue: two int loads from the precomputed bound array.
    if (t < 2) sBounds[t] = g_bound[g + t];
    __syncthreads();

    const int s = sBounds[0];
    const int e = sBounds[1];
    const int cnt = e - s;
    // NOTE: no early return — cluster.sync below requires all CTAs.

    // This rank's rows: s + rank*8 + r, stride 16. Iteration count:
    const int row0 = s + rank * 8 + r;
    const int nIter = (e > row0) ? ((e - row0 + 15) >> 4) : 0;
    const ptrdiff_t STRIDE = (ptrdiff_t)16 * 32;   // 16 rows of 32 float4

    float4 sum = make_float4(0.f, 0.f, 0.f, 0.f);
    float4 sq  = make_float4(0.f, 0.f, 0.f, 0.f);

    // Pass 1: plain loads — the ONLY L2 allocators in this kernel.
    {
        const float4* p = (const float4*)x + (size_t)row0 * 32 + q;
        for (int k = 0; k < nIter; k++, p += STRIDE) {
            float4 v = *p;
            sum.x += v.x; sum.y += v.y; sum.z += v.z; sum.w += v.w;
            sq.x  += v.x * v.x; sq.y += v.y * v.y;
            sq.z  += v.z * v.z; sq.w += v.w * v.w;
        }
    }
    s_sum[r][q] = sum;
    s_sq [r][q] = sq;
    __syncthreads();

    // Cross-warp tree reduce over the 8 row-lanes.
    #pragma unroll
    for (int off = 4; off > 0; off >>= 1) {
        if (r < off) {
            float4 a = s_sum[r][q], b = s_sum[r + off][q];
            a.x += b.x; a.y += b.y; a.z += b.z; a.w += b.w;
            s_sum[r][q] = a;
            float4 c = s_sq[r][q], d = s_sq[r + off][q];
            c.x += d.x; c.y += d.y; c.z += d.z; c.w += d.w;
            s_sq[r][q] = c;
        }
        __syncthreads();
    }

    // Exchange CTA partials with the peer rank via DSMEM.
    {
        const int c = t & 127;
        const int h = t >> 7;        // 0: sum, 1: sq
        const float* own = (h == 0) ? (const float*)&s_sum[0][0]
                                    : (const float*)&s_sq[0][0];
        uint32_t laddr = (uint32_t)__cvta_generic_to_shared(&s_peer[h][c]);
        st_peer_f32(laddr, rank ^ 1, own[c]);
        cluster_sync_();             // peer's partials now in s_peer
    }

    // Warp 0: combine halves, per-column affine coefficients A, B.
    if (r == 0 && cnt > 0) {
        float inv_cnt = 1.f / (float)cnt;
        const float* psum = &s_peer[0][q * 4];
        const float* psq  = &s_peer[1][q * 4];
        float4 tsum = s_sum[0][q];
        float4 tsq  = s_sq [0][q];
        tsum.x += psum[0]; tsum.y += psum[1]; tsum.z += psum[2]; tsum.w += psum[3];
        tsq.x  += psq[0];  tsq.y  += psq[1];  tsq.z  += psq[2];  tsq.w  += psq[3];
        float4 w4   = ((const float4*)weight)[q];
        float4 b4   = ((const float4*)bias)[q];
        float4 ms4  = ((const float4*)mean_scale)[q];

        float4 A, B;
        {
            float m = tsum.x * inv_cnt;
            float var = tsq.x * inv_cnt + m * m * ms4.x * (ms4.x - 2.f);
            A.x = w4.x * rsqrtf(var + EPS);
            B.x = b4.x - m * ms4.x * A.x;
        }
        {
            float m = tsum.y * inv_cnt;
            float var = tsq.y * inv_cnt + m * m * ms4.y * (ms4.y - 2.f);
            A.y = w4.y * rsqrtf(var + EPS);
            B.y = b4.y - m * ms4.y * A.y;
        }
        {
            float m = tsum.z * inv_cnt;
            float var = tsq.z * inv_cnt + m * m * ms4.z * (ms4.z - 2.f);
            A.z = w4.z * rsqrtf(var + EPS);
            B.z = b4.z - m * ms4.z * A.z;
        }
        {
            float m = tsum.w * inv_cnt;
            float var = tsq.w * inv_cnt + m * m * ms4.w * (ms4.w - 2.f);
            A.w = w4.w * rsqrtf(var + EPS);
            B.w = b4.w - m * ms4.w * A.w;
        }
        sA[q] = A;
        sB[q] = B;
    }
    __syncthreads();

    const float4 A = sA[q];
    const float4 B = sB[q];
    const uint64_t pol = mk_policy_evict_first();

    // Pass 2: non-allocating loads (hit pass-1 lines, demote) + streaming
    // stores — neither inserts long-lived L2 lines.
    {
        const float4* p  = (const float4*)x + (size_t)row0 * 32 + q;
        float4*       op = (float4*)out     + (size_t)row0 * 32 + q;
        for (int k = 0; k < nIter; k++, p += STRIDE, op += STRIDE) {
            float4 v = ld4_ef(p, pol);
            float4 o;
            o.x = v.x * A.x + B.x;
            o.y = v.y * A.y + B.y;
            o.z = v.z * A.z + B.z;
            o.w = v.w * A.w + B.w;
            st4_stream(op, o);
        }
    }
}

extern "C" void kernel_launch(void* const* d_in, const int* in_sizes, int n_in,
                              void* d_out, int out_size) {
    const float* x          = (const float*)d_in[0];
    const void*  batch      = (const void*)d_in[1];
    // d_in[2] = num_segments (device scalar; grid sized by NUM_SEGMENTS)
    const float* weight     = (const float*)d_in[3];
    const float* bias       = (const float*)d_in[4];
    const float* mean_scale = (const float*)d_in[5];
    float*       out        = (float*)d_out;

    const int D = 128;
    const int N = in_sizes[0] / D;

    const int n4 = (N + 3) / 4;   // elements handled 4-per-thread
    find_bounds_kernel<<<(n4 + 255) / 256, 256>>>(batch, N);
    // 2 CTAs per segment (cluster pairs: blockIdx {2g, 2g+1}).
    graphnorm_kernel<<<NUM_SEGMENTS * 2, 256>>>(x, weight, bias,
                                                mean_scale, out);
}